// round 10
// baseline (speedup 1.0000x reference)
#include <cuda_runtime.h>
#include <cuda_fp16.h>

// Shapes fixed by dataset: x(32,3,720,1280) f32, flow(30,2,720,1280) f32,
// out(30,6,720,1280) f32.
constexpr int T = 32, C = 3, H = 720, W = 1280;
constexpr int N = T - 2;                        // 30
constexpr long long HW = (long long)H * W;      // 921600
constexpr int TILES = (int)(HW / 256);          // 3600

// Channel-interleaved fp16 copy of x: 8 B/px = {h(c0),h(c1)},{h(c2),0}.
__device__ uint2 g_xp[(long long)T * HW];

// ───────── K1: repack 2 frames (tA, tB) CHW fp32 -> HWC4 fp16 ───────────────
__global__ __launch_bounds__(256)
void repack2_kernel(const float* __restrict__ x, int tA, int tB)
{
    const int t = blockIdx.y ? tB : tA;
    const long long p4 = (long long)blockIdx.x * blockDim.x + threadIdx.x;
    if (p4 >= HW / 4) return;
    const long long p = p4 * 4;

    const float* __restrict__ src = x + (long long)t * C * HW + p;
    const float4 c0 = *(const float4*)(src);
    const float4 c1 = *(const float4*)(src + HW);
    const float4 c2 = *(const float4*)(src + 2 * HW);

    const float c0a[4] = {c0.x, c0.y, c0.z, c0.w};
    const float c1a[4] = {c1.x, c1.y, c1.z, c1.w};
    const float c2a[4] = {c2.x, c2.y, c2.z, c2.w};

    uint2 px[4];
#pragma unroll
    for (int j = 0; j < 4; ++j) {
        __half2 h01 = __floats2half2_rn(c0a[j], c1a[j]);
        __half2 h2z = __floats2half2_rn(c2a[j], 0.f);
        px[j].x = *(const unsigned int*)&h01;
        px[j].y = *(const unsigned int*)&h2z;
    }
    uint4* __restrict__ dst = (uint4*)(g_xp + (long long)t * HW + p);
    dst[0] = make_uint4(px[0].x, px[0].y, px[1].x, px[1].y);
    dst[1] = make_uint4(px[2].x, px[2].y, px[3].x, px[3].y);
}

// ───────── K2: one z-pair per launch, 1 px/thread, loads-first ──────────────
// Pair (n, nb=N-1-n): flow[n] supplies fwd(n) AND bwd(nb); flow[nb] supplies
// bwd(n) AND fwd(nb).  off = (side == dir) ? offF : offB  (validated R4/R6).
__global__ __launch_bounds__(256, 8)
void diff_kernel(const float* __restrict__ flow,
                 float* __restrict__ out, int z)
{
    const int n  = z, nb = N - 1 - z;
    const int p  = blockIdx.x * blockDim.x + threadIdx.x;  // pixel index
    const int w  = p % W;
    const int h  = p / W;
    const long long hw = p;

    const float* fF = flow + (long long)(2 * n) * HW;
    const float* fB = flow + (long long)(2 * nb) * HW;
    const float dxF = fF[hw];
    const float dyF = fF[HW + hw];
    const float dxB = fB[hw];
    const float dyB = fB[HW + hw];

    int offF, offB;
    {
        int ih = __float2int_rn((float)h + dxF);
        ih = min(max(ih, 0), H - 1);
        int iw = __float2int_rn((float)w + dyF);
        iw = min(max(iw, 0), W - 1);
        offF = ih * W + iw;

        int ihb = __float2int_rn((float)h + dxB);
        ihb = min(max(ihb, 0), H - 1);
        int iwb = __float2int_rn((float)w + dyB);
        iwb = min(max(iwb, 0), W - 1);
        offB = ihb * W + iwb;
    }

    // Issue ALL loads first: 4 divergent gathers + 2 center LDG.64
    uint2 gv[4];
    uint2 cv[2];
#pragma unroll
    for (int side = 0; side < 2; ++side) {
        const int no = side ? nb : n;
#pragma unroll
        for (int dir = 0; dir < 2; ++dir) {
            const int srcT = dir ? no : no + 2;
            const int off  = (side == dir) ? offF : offB;
            gv[side * 2 + dir] = __ldg(g_xp + (long long)srcT * HW + off);
        }
        cv[side] = g_xp[(long long)(no + 1) * HW + hw];
    }

#pragma unroll
    for (int side = 0; side < 2; ++side) {
        const int no = side ? nb : n;
        const __half2 c01 = *(const __half2*)&cv[side].x;
        const __half2 c2z = *(const __half2*)&cv[side].y;
        const float cc0 = __low2float(c01);
        const float cc1 = __high2float(c01);
        const float cc2 = __low2float(c2z);
#pragma unroll
        for (int dir = 0; dir < 2; ++dir) {
            const uint2 g8 = gv[side * 2 + dir];
            const __half2 g01 = *(const __half2*)&g8.x;
            const __half2 g2z = *(const __half2*)&g8.y;
            float* __restrict__ op =
                out + (long long)(no * 6 + dir * 3) * HW + hw;
            op[0]      = cc0 - __low2float(g01);
            op[HW]     = cc1 - __high2float(g01);
            op[2 * HW] = cc2 - __low2float(g2z);
        }
    }
}

// ───────── launch: fine-grained pipelined overlap ───────────────────────────
// K2(z) needs xp frames {z..z+2} U {29-z..31-z}.
// Seed (hi-pri): frames {0,1,2,29,30,31}. Side (LOW-pri): 13 two-frame
// segments {2+k, 29-k}, k=1..13, each recording ev[k]. K2(z) on hi-pri waits
// ev[min(z,13)] (z>=1). Low priority keeps K1 out of K2's CTA slots (R8 bug).
extern "C" void kernel_launch(void* const* d_in, const int* in_sizes, int n_in,
                              void* d_out, int out_size)
{
    const float* x    = (const float*)d_in[0];
    const float* flow = (const float*)d_in[1];
    float* out        = (float*)d_out;

    static cudaStream_t s1 = nullptr, s2 = nullptr;   // hi-pri K2, low-pri K1
    static cudaEvent_t evFork = nullptr, evDone = nullptr, ev[14];
    if (!s1) {
        int loPri, hiPri;
        cudaDeviceGetStreamPriorityRange(&loPri, &hiPri);
        cudaStreamCreateWithPriority(&s1, cudaStreamNonBlocking, hiPri);
        cudaStreamCreateWithPriority(&s2, cudaStreamNonBlocking, loPri);
        cudaEventCreateWithFlags(&evFork, cudaEventDisableTiming);
        cudaEventCreateWithFlags(&evDone, cudaEventDisableTiming);
        for (int k = 1; k <= 13; ++k)
            cudaEventCreateWithFlags(&ev[k], cudaEventDisableTiming);
    }

    const dim3 g2(900, 2);   // repack2: 2 frames per launch

    // Fork both worker streams off the capture stream.
    cudaEventRecord(evFork, 0);
    cudaStreamWaitEvent(s1, evFork, 0);
    cudaStreamWaitEvent(s2, evFork, 0);

    // Low-pri K1 segments, ends-inward.
    for (int k = 1; k <= 13; ++k) {
        repack2_kernel<<<g2, 256, 0, s2>>>(x, 2 + k, 29 - k);
        cudaEventRecord(ev[k], s2);
    }

    // Hi-pri: seed frames, then the 15 K2 z-launches.
    repack2_kernel<<<g2, 256, 0, s1>>>(x, 0, 31);
    repack2_kernel<<<g2, 256, 0, s1>>>(x, 1, 30);
    repack2_kernel<<<g2, 256, 0, s1>>>(x, 2, 29);

    for (int z = 0; z < 15; ++z) {
        if (z >= 1)
            cudaStreamWaitEvent(s1, ev[z < 13 ? z : 13], 0);
        diff_kernel<<<TILES, 256, 0, s1>>>(flow, out, z);
    }

    // Join back to the capture stream.
    cudaEventRecord(evDone, s1);
    cudaStreamWaitEvent(0, evDone, 0);
}

// round 11
// speedup vs baseline: 1.3466x; 1.3466x over previous
#include <cuda_runtime.h>
#include <cuda_fp16.h>

// Shapes fixed by dataset: x(32,3,720,1280) f32, flow(30,2,720,1280) f32,
// out(30,6,720,1280) f32.
constexpr int T = 32, C = 3, H = 720, W = 1280;
constexpr int N = T - 2;                        // 30
constexpr long long HW = (long long)H * W;      // 921600
constexpr int NPAIR = N / 2;                    // 15
constexpr int TILES = (int)(HW / 256);          // 3600

// Mirror-paired fp16 planes: plane p pixel = 16B =
//   { h(frame p c0), h(c1) | h(c2), 0 | h(frame 31-p c0), h(c1) | h(c2), 0 }
// One divergent LDG.128 serves BOTH mirror-frame gathers. 236 MB scratch.
__device__ uint4 g_xp2[(long long)(T / 2) * HW];

// ───────── K1: repack frames (p, 31-p) -> paired plane p ────────────────────
__global__ __launch_bounds__(256)
void repack_kernel(const float* __restrict__ x)
{
    const int p = blockIdx.y;                   // 0..15
    const long long p4 = (long long)blockIdx.x * blockDim.x + threadIdx.x;
    if (p4 >= HW / 4) return;
    const long long px = p4 * 4;

    const float* __restrict__ srcA = x + (long long)p * C * HW + px;
    const float* __restrict__ srcB = x + (long long)(31 - p) * C * HW + px;
    const float4 a0 = *(const float4*)(srcA);
    const float4 a1 = *(const float4*)(srcA + HW);
    const float4 a2 = *(const float4*)(srcA + 2 * HW);
    const float4 b0 = *(const float4*)(srcB);
    const float4 b1 = *(const float4*)(srcB + HW);
    const float4 b2 = *(const float4*)(srcB + 2 * HW);

    const float a0a[4] = {a0.x, a0.y, a0.z, a0.w};
    const float a1a[4] = {a1.x, a1.y, a1.z, a1.w};
    const float a2a[4] = {a2.x, a2.y, a2.z, a2.w};
    const float b0a[4] = {b0.x, b0.y, b0.z, b0.w};
    const float b1a[4] = {b1.x, b1.y, b1.z, b1.w};
    const float b2a[4] = {b2.x, b2.y, b2.z, b2.w};

    uint4* __restrict__ dst = g_xp2 + (long long)p * HW + px;
#pragma unroll
    for (int j = 0; j < 4; ++j) {
        __half2 w0 = __floats2half2_rn(a0a[j], a1a[j]);
        __half2 w1 = __floats2half2_rn(a2a[j], 0.f);
        __half2 w2 = __floats2half2_rn(b0a[j], b1a[j]);
        __half2 w3 = __floats2half2_rn(b2a[j], 0.f);
        dst[j] = make_uint4(*(const unsigned int*)&w0, *(const unsigned int*)&w1,
                            *(const unsigned int*)&w2, *(const unsigned int*)&w3);
    }
}

// ───────── K2: paired flow-diff, mirror-plane gathers, 1 px/thread ──────────
// z-pair (n=z, nb=29-z). offF from flow[n], offB from flow[nb] (R4/R6 table):
//   offF gathers frames {z+2 (fwd n), 29-z (bwd nb)}  = mirror pair -> 1 LDG.128
//   offB gathers frames {z (bwd n), 31-z (fwd nb)}    = mirror pair -> 1 LDG.128
//   centers are frames {z+1, 30-z}                    = mirror pair -> 1 LDG.128
__global__ __launch_bounds__(256, 8)
void diff_kernel(const float* __restrict__ flow,
                 float* __restrict__ out)
{
    const int z  = blockIdx.x;                  // z fastest for L2 gather reuse
    const int n  = z, nb = N - 1 - z;
    const int p  = blockIdx.y * blockDim.x + threadIdx.x;  // pixel index
    const int w  = p % W;
    const int h  = p / W;
    const long long hw = p;

    const float* fF = flow + (long long)(2 * n) * HW;
    const float* fB = flow + (long long)(2 * nb) * HW;
    const float dxF = fF[hw];
    const float dyF = fF[HW + hw];
    const float dxB = fB[hw];
    const float dyB = fB[HW + hw];

    int offF, offB;
    {
        int ih = __float2int_rn((float)h + dxF);
        ih = min(max(ih, 0), H - 1);
        int iw = __float2int_rn((float)w + dyF);
        iw = min(max(iw, 0), W - 1);
        offF = ih * W + iw;

        int ihb = __float2int_rn((float)h + dxB);
        ihb = min(max(ihb, 0), H - 1);
        int iwb = __float2int_rn((float)w + dyB);
        iwb = min(max(iwb, 0), W - 1);
        offB = ihb * W + iwb;
    }

    // Plane for offF: frames {z+2, 29-z}; stored at min(z+2, 29-z)... for
    // z<=13 plane z+2 (lo=z+2). z=14: frames {16,15} -> plane 15, lo=15 (swap).
    const int tF  = z + 2;
    const int pF  = (tF <= 15) ? tF : 31 - tF;
    const bool sw = (tF > 15);

    // ── Issue all 3 LDG.128 loads first ──
    const uint4 gF = __ldg(g_xp2 + (long long)pF * HW + offF);
    const uint4 gB = __ldg(g_xp2 + (long long)z * HW + offB);       // plane z: lo=z, hi=31-z
    const uint4 cv = __ldg(g_xp2 + (long long)(z + 1) * HW + hw);   // lo=z+1, hi=30-z

    // Decode helpers: (w0,w1) -> 3 floats
#define DEC3(u0, u1, r0, r1, r2)                            \
    {                                                       \
        const __half2 _h01 = *(const __half2*)&(u0);        \
        const __half2 _h2z = *(const __half2*)&(u1);        \
        r0 = __low2float(_h01);                             \
        r1 = __high2float(_h01);                            \
        r2 = __low2float(_h2z);                             \
    }

    float cnA0, cnA1, cnA2, cnB0, cnB1, cnB2;               // centers n, nb
    DEC3(cv.x, cv.y, cnA0, cnA1, cnA2);
    DEC3(cv.z, cv.w, cnB0, cnB1, cnB2);

    float fLo0, fLo1, fLo2, fHi0, fHi1, fHi2;               // offF gathers
    DEC3(gF.x, gF.y, fLo0, fLo1, fLo2);
    DEC3(gF.z, gF.w, fHi0, fHi1, fHi2);
    // fwd(n) = frame z+2 ; bwd(nb) = frame 29-z
    const float fwdN0 = sw ? fHi0 : fLo0, fwdN1 = sw ? fHi1 : fLo1, fwdN2 = sw ? fHi2 : fLo2;
    const float bwdB0 = sw ? fLo0 : fHi0, bwdB1 = sw ? fLo1 : fHi1, bwdB2 = sw ? fLo2 : fHi2;

    float bwdN0, bwdN1, bwdN2, fwdB0, fwdB1, fwdB2;         // offB gathers
    DEC3(gB.x, gB.y, bwdN0, bwdN1, bwdN2);                  // lo = frame z   = bwd(n)
    DEC3(gB.z, gB.w, fwdB0, fwdB1, fwdB2);                  // hi = frame 31-z = fwd(nb)
#undef DEC3

    // ── Stores: 4 output trios, all coalesced ──
    float* __restrict__ oFn = out + (long long)(n * 6) * HW + hw;
    oFn[0]      = cnA0 - fwdN0;
    oFn[HW]     = cnA1 - fwdN1;
    oFn[2 * HW] = cnA2 - fwdN2;

    float* __restrict__ oBn = out + (long long)(n * 6 + 3) * HW + hw;
    oBn[0]      = cnA0 - bwdN0;
    oBn[HW]     = cnA1 - bwdN1;
    oBn[2 * HW] = cnA2 - bwdN2;

    float* __restrict__ oFb = out + (long long)(nb * 6) * HW + hw;
    oFb[0]      = cnB0 - fwdB0;
    oFb[HW]     = cnB1 - fwdB1;
    oFb[2 * HW] = cnB2 - fwdB2;

    float* __restrict__ oBb = out + (long long)(nb * 6 + 3) * HW + hw;
    oBb[0]      = cnB0 - bwdB0;
    oBb[HW]     = cnB1 - bwdB1;
    oBb[2 * HW] = cnB2 - bwdB2;
}

// ───────── launch ───────────────────────────────────────────────────────────
extern "C" void kernel_launch(void* const* d_in, const int* in_sizes, int n_in,
                              void* d_out, int out_size)
{
    const float* x    = (const float*)d_in[0];
    const float* flow = (const float*)d_in[1];
    float* out        = (float*)d_out;

    {   // K1: repack x into mirror-paired fp16 planes
        dim3 grid((unsigned)((HW / 4 + 255) / 256), T / 2);   // (900, 16)
        repack_kernel<<<grid, 256>>>(x);
    }
    {   // K2: paired flow-diff, z fastest for cross-z L2 gather reuse
        dim3 grid(NPAIR, TILES);   // (15, 3600)
        diff_kernel<<<grid, 256>>>(flow, out);
    }
}